// round 13
// baseline (speedup 1.0000x reference)
#include <cuda_runtime.h>
#include <cuda_bf16.h>
#include <cstdint>

#define NN   50000
#define NE   800000
#define DIN  128
#define DH   256
#define NG   256
#define DH2  128

// ---------------- scratch (device globals; no allocations allowed) ----------
__device__ __nv_bfloat16 g_hb [(size_t)NN * DIN];  // input h, bf16
__device__ __nv_bfloat16 g_a  [(size_t)NN * DH];   // aggregated features, bf16
__device__ __nv_bfloat16 g_h1 [(size_t)NN * DH];   // layer-1 output, bf16
__device__ __nv_bfloat16 g_h2 [(size_t)NN * DH];   // layer-2 output, bf16
__device__ __nv_bfloat16 g_w1 [DH * DIN];          // W1^T bf16
__device__ __nv_bfloat16 g_w2 [DH * DH];           // W2^T bf16
__device__ int g_deg[NN];
__device__ int g_rowptr[NN + 1];
__device__ int g_pos[NN];
__device__ int g_esrc[NE];

// ---------------- helpers ---------------------------------------------------
__device__ __forceinline__ uint32_t smem_u32(const void* p) {
    uint32_t a;
    asm("{ .reg .u64 t; cvta.to.shared.u64 t, %1; cvt.u32.u64 %0, t; }"
        : "=r"(a) : "l"(p));
    return a;
}

__device__ __forceinline__ void ldm_x4(uint32_t* f, uint32_t sa) {
    asm volatile("ldmatrix.sync.aligned.m8n8.x4.shared.b16 {%0,%1,%2,%3}, [%4];"
                 : "=r"(f[0]), "=r"(f[1]), "=r"(f[2]), "=r"(f[3]) : "r"(sa));
}

__device__ __forceinline__ void mma16816(float* c, const uint32_t* a, const uint32_t* b) {
    asm volatile(
        "mma.sync.aligned.m16n8k16.row.col.f32.bf16.bf16.f32 "
        "{%0,%1,%2,%3}, {%4,%5,%6,%7}, {%8,%9}, {%0,%1,%2,%3};"
        : "+f"(c[0]), "+f"(c[1]), "+f"(c[2]), "+f"(c[3])
        : "r"(a[0]), "r"(a[1]), "r"(a[2]), "r"(a[3]), "r"(b[0]), "r"(b[1]));
}

__device__ __forceinline__ void cp16(uint32_t d, const void* s, bool p) {
    asm volatile("cp.async.cg.shared.global [%0], [%1], 16, %2;"
                 :: "r"(d), "l"(s), "r"(p ? 16 : 0));
}
__device__ __forceinline__ void cp_commit() { asm volatile("cp.async.commit_group;"); }
template <int N>
__device__ __forceinline__ void cp_wait() { asm volatile("cp.async.wait_group %0;" :: "n"(N)); }

__device__ __forceinline__ void acc_u1(float* acc, uint32_t u) {
    float2 a = __bfloat1622float2(*(__nv_bfloat162*)&u);
    acc[0] += a.x; acc[1] += a.y;
}
__device__ __forceinline__ void acc_u2(float* acc, uint2 u) {
    float2 a = __bfloat1622float2(*(__nv_bfloat162*)&u.x);
    float2 b = __bfloat1622float2(*(__nv_bfloat162*)&u.y);
    acc[0] += a.x; acc[1] += a.y; acc[2] += b.x; acc[3] += b.y;
}

__device__ __forceinline__ void conv_h_item(const float* __restrict__ h, int i) {
    float4 v = __ldg((const float4*)h + i);
    __nv_bfloat16 b[4] = { __float2bfloat16(v.x), __float2bfloat16(v.y),
                           __float2bfloat16(v.z), __float2bfloat16(v.w) };
    *(uint2*)(g_hb + 4 * (size_t)i) = *(uint2*)b;
}

// ---- h-conversion split between scan and scatter kernels -------------------
#define PREP_H_ITEMS   (NN * DIN / 4)            // 1,600,000 float4 items
#define H1_ITEMS       614400                    // done inside k_scan_conv
#define H2_ITEMS       (PREP_H_ITEMS - H1_ITEMS) // done inside k_scatter_conv
#define PREP_W1_ITEMS  (DH * DIN)                // 32,768
#define PREP_W2_ITEMS  (DH * DH)                 // 65,536
#define ZW_TOTAL       (NN + PREP_W1_ITEMS + PREP_W2_ITEMS)

// ---------------- zero degree + W transposes --------------------------------
__global__ void k_zero_w(const float* __restrict__ W1, const float* __restrict__ W2) {
    int i = blockIdx.x * blockDim.x + threadIdx.x;
    if (i < NN) { g_deg[i] = 0; return; }
    i -= NN;
    if (i < PREP_W1_ITEMS) {
        int n = i / DIN, k = i % DIN;
        g_w1[i] = __float2bfloat16(W1[(size_t)k * DH + n]);
        return;
    }
    i -= PREP_W1_ITEMS;
    if (i < PREP_W2_ITEMS) {
        int n = i / DH, k = i % DH;
        g_w2[i] = __float2bfloat16(W2[(size_t)k * DH + n]);
    }
}

// ---------------- edge histogram --------------------------------------------
__global__ void k_hist(const int* __restrict__ dst) {
    int e = blockIdx.x * blockDim.x + threadIdx.x;
    if (e < NE) atomicAdd(&g_deg[dst[e]], 1);
}

// -------- scan (block 0) + h->bf16 conversion part 1 (blocks 1..) -----------
#define SCAN_CONV_BLKS (1 + (H1_ITEMS + 1023) / 1024)   // 601

__global__ void k_scan_conv(const float* __restrict__ h) {
    if (blockIdx.x > 0) {
        int idx = (blockIdx.x - 1) * 1024 + threadIdx.x;
        if (idx < H1_ITEMS) conv_h_item(h, idx);
        return;
    }
    // chunked single-block scan: 1024 threads * 49 elems
    const int CH = 49;
    int t = threadIdx.x;
    int beg = t * CH;
    int end = beg + CH; if (end > NN) end = NN;
    int s = 0;
    for (int i = beg; i < end; ++i) s += g_deg[i];
    int lane = t & 31, w = t >> 5;
    int v = s;
#pragma unroll
    for (int o = 1; o < 32; o <<= 1) {
        int u = __shfl_up_sync(0xffffffffu, v, o);
        if (lane >= o) v += u;
    }
    __shared__ int wsum[32];
    if (lane == 31) wsum[w] = v;
    __syncthreads();
    if (w == 0) {
        int x = wsum[lane];
#pragma unroll
        for (int o = 1; o < 32; o <<= 1) {
            int u = __shfl_up_sync(0xffffffffu, x, o);
            if (lane >= o) x += u;
        }
        wsum[lane] = x;
    }
    __syncthreads();
    int excl = v - s + (w > 0 ? wsum[w - 1] : 0);
    for (int i = beg; i < end; ++i) {
        int d = g_deg[i];
        g_rowptr[i] = excl;
        g_pos[i]    = excl;
        excl += d;
    }
    if (t == 1023) g_rowptr[NN] = wsum[31];
}

// -------- scatter + h->bf16 conversion part 2 --------------------------------
#define SCAT_BLKS      ((NE + 1023) / 1024)             // 782
#define SCAT_CONV_BLKS (SCAT_BLKS + (H2_ITEMS + 1023) / 1024)

__global__ void k_scatter_conv(const int* __restrict__ src, const int* __restrict__ dst,
                               const float* __restrict__ h) {
    if (blockIdx.x < SCAT_BLKS) {
        int e = blockIdx.x * 1024 + threadIdx.x;
        if (e < NE) {
            int p = atomicAdd(&g_pos[dst[e]], 1);
            g_esrc[p] = src[e];
        }
        return;
    }
    int idx = (blockIdx.x - SCAT_BLKS) * 1024 + threadIdx.x + H1_ITEMS;
    if (idx < PREP_H_ITEMS) conv_h_item(h, idx);
}

// ---- mean aggregation: 2 warps per node (each owns F/2 features) ------------
// F=128: V=2 (uint, 1 line/warp-load); F=256: V=4 (uint2, 2 lines/warp-load)
template <int F>
__global__ __launch_bounds__(256) void k_agg(const __nv_bfloat16* __restrict__ hin,
                                             __nv_bfloat16* __restrict__ outp) {
    int gw = (blockIdx.x * blockDim.x + threadIdx.x) >> 5;   // global warp
    int node = gw >> 1;
    if (node >= NN) return;
    int half = gw & 1;
    int lane = threadIdx.x & 31;
    int beg = g_rowptr[node];
    int end = g_rowptr[node + 1];
    constexpr int V = F / 64;          // bf16 per lane: 2 or 4
    float acc[V];
#pragma unroll
    for (int j = 0; j < V; ++j) acc[j] = 0.f;

    const size_t lo = (size_t)half * (F / 2) + (size_t)lane * V;
    int e = beg;
    for (; e + 3 < end; e += 4) {
        int s0 = g_esrc[e], s1 = g_esrc[e + 1], s2 = g_esrc[e + 2], s3 = g_esrc[e + 3];
        if constexpr (V == 2) {
            uint32_t u0 = __ldg((const uint32_t*)(hin + (size_t)s0 * F + lo));
            uint32_t u1 = __ldg((const uint32_t*)(hin + (size_t)s1 * F + lo));
            uint32_t u2 = __ldg((const uint32_t*)(hin + (size_t)s2 * F + lo));
            uint32_t u3 = __ldg((const uint32_t*)(hin + (size_t)s3 * F + lo));
            acc_u1(acc, u0); acc_u1(acc, u1); acc_u1(acc, u2); acc_u1(acc, u3);
        } else {
            uint2 u0 = __ldg((const uint2*)(hin + (size_t)s0 * F + lo));
            uint2 u1 = __ldg((const uint2*)(hin + (size_t)s1 * F + lo));
            uint2 u2 = __ldg((const uint2*)(hin + (size_t)s2 * F + lo));
            uint2 u3 = __ldg((const uint2*)(hin + (size_t)s3 * F + lo));
            acc_u2(acc, u0); acc_u2(acc, u1); acc_u2(acc, u2); acc_u2(acc, u3);
        }
    }
    for (; e < end; ++e) {
        int s0 = g_esrc[e];
        if constexpr (V == 2) {
            uint32_t u0 = __ldg((const uint32_t*)(hin + (size_t)s0 * F + lo));
            acc_u1(acc, u0);
        } else {
            uint2 u0 = __ldg((const uint2*)(hin + (size_t)s0 * F + lo));
            acc_u2(acc, u0);
        }
    }
    float inv = (end > beg) ? (1.f / (float)(end - beg)) : 0.f;
    __nv_bfloat16 o[V];
#pragma unroll
    for (int j = 0; j < V; ++j) o[j] = __float2bfloat16(acc[j] * inv);
    if constexpr (V == 2)
        *(uint32_t*)(outp + (size_t)node * F + lo) = *(uint32_t*)o;
    else
        *(uint2*)(outp + (size_t)node * F + lo) = *(uint2*)o;
}

// ------- HMMA GEMM (cp.async 2-stage, BK=64): C = relu(A@B^T + b) -----------
// A: [NN x K] bf16; B: [256 x K] bf16; C: [NN x 256] bf16
#define LDA      72                 // 64 + 8 pad (bf16); row stride 144 B
#define TILE_B   (128 * LDA * 2)    // 18432 bytes
#define STAGE_B  (2 * TILE_B)       // 36864 bytes: A, B
#define GEMM_SMEM (2 * STAGE_B)     // 73728 bytes

template <int K>
__global__ __launch_bounds__(256, 2) void k_gemm_hmma(
    const __nv_bfloat16* __restrict__ A, const __nv_bfloat16* __restrict__ B,
    const float* __restrict__ bias, __nv_bfloat16* __restrict__ C)
{
    extern __shared__ char dsm[];
    const uint32_t sb0 = smem_u32(dsm);

    const int tid  = threadIdx.x;
    const int lane = tid & 31;
    const int wid  = tid >> 5;
    const int wm   = (wid >> 1) * 32;
    const int wn   = (wid & 1) * 64;
    const int m0   = blockIdx.x * 128;
    const int n0   = blockIdx.y * 128;

    float c[2][8][4];
#pragma unroll
    for (int i = 0; i < 2; ++i)
#pragma unroll
        for (int j = 0; j < 8; ++j)
#pragma unroll
            for (int q = 0; q < 4; ++q) c[i][j][q] = 0.f;

    const int aq = lane >> 3, ar = lane & 7;
    const int a_row = ar + (aq & 1) * 8;
    const int a_col = (aq >> 1) * 8;
    uint32_t aoff[2];
#pragma unroll
    for (int i = 0; i < 2; ++i)
        aoff[i] = (uint32_t)(((wm + i * 16 + a_row) * LDA + a_col) * 2);
    const int b_row = (aq >> 1) * 8 + ar;
    const int b_col = (aq & 1) * 8;
    uint32_t boff[4];
#pragma unroll
    for (int jp = 0; jp < 4; ++jp)
        boff[jp] = (uint32_t)(((wn + jp * 16 + b_row) * LDA + b_col) * 2);

    auto load_stage = [&](int k0, int s) {
        uint32_t base = sb0 + (uint32_t)s * STAGE_B;
#pragma unroll
        for (int t = 0; t < 4; ++t) {
            int idx = t * 256 + tid;          // 0..1023: 128 rows x 64 cols
            int r = idx >> 3, cB = (idx & 7) * 8;
            uint32_t so = (uint32_t)((r * LDA + cB) * 2);
            int gr = m0 + r;
            bool ap = gr < NN;
            int grc = ap ? gr : (NN - 1);
            cp16(base + so, A + (size_t)grc * K + k0 + cB, ap);
            cp16(base + TILE_B + so, B + (size_t)(n0 + r) * K + k0 + cB, true);
        }
        cp_commit();
    };

    const int NCH = K / 64;                  // 2 or 4
    load_stage(0, 0);
    load_stage(64, 1);
    for (int ch = 0; ch < NCH; ++ch) {
        if (ch + 1 < NCH) cp_wait<1>(); else cp_wait<0>();
        __syncthreads();
        uint32_t base = sb0 + (uint32_t)(ch & 1) * STAGE_B;
        uint32_t sa = base, sbm = base + TILE_B;
#pragma unroll
        for (int ks = 0; ks < 4; ++ks) {
            uint32_t af[2][4];
#pragma unroll
            for (int i = 0; i < 2; ++i) ldm_x4(af[i], sa + aoff[i] + ks * 32);
#pragma unroll
            for (int jp = 0; jp < 4; ++jp) {
                uint32_t bf[4];
                ldm_x4(bf, sbm + boff[jp] + ks * 32);
#pragma unroll
                for (int i = 0; i < 2; ++i) {
#pragma unroll
                    for (int jj = 0; jj < 2; ++jj)
                        mma16816(c[i][jp * 2 + jj], af[i], bf + jj * 2);
                }
            }
        }
        __syncthreads();
        if (ch + 2 < NCH) load_stage((ch + 2) * 64, ch & 1);
    }

    // epilogue: bias + relu, bf16 store
    const int g   = lane >> 2;
    const int tig = lane & 3;
#pragma unroll
    for (int i = 0; i < 2; ++i) {
#pragma unroll
        for (int j = 0; j < 8; ++j) {
            int col  = n0 + wn + j * 8 + 2 * tig;
            float b0 = bias[col], b1 = bias[col + 1];
            int r0 = m0 + wm + i * 16 + g;
            if (r0 < NN) {
                __nv_bfloat162 o = __floats2bfloat162_rn(
                    fmaxf(c[i][j][0] + b0, 0.f), fmaxf(c[i][j][1] + b1, 0.f));
                *(__nv_bfloat162*)(C + (size_t)r0 * 256 + col) = o;
            }
            int r1 = r0 + 8;
            if (r1 < NN) {
                __nv_bfloat162 o = __floats2bfloat162_rn(
                    fmaxf(c[i][j][2] + b0, 0.f), fmaxf(c[i][j][3] + b1, 0.f));
                *(__nv_bfloat162*)(C + (size_t)r1 * 256 + col) = o;
            }
        }
    }
}

// -------- fused per-graph readout + MLP (graph_ids sorted) ------------------
__global__ __launch_bounds__(256) void k_readout_mlp(
    const int* __restrict__ gids,
    const float* __restrict__ Wr1, const float* __restrict__ br1,
    const float* __restrict__ Wr2, const float* __restrict__ br2,
    float* __restrict__ out)
{
    int g = blockIdx.x;
    int f = threadIdx.x;                 // 256 threads
    __shared__ int sb_, se_;
    __shared__ float shg[DH];
    __shared__ float ws[4];
    if (f == 0) {
        int lo = 0, hi = NN;
        while (lo < hi) { int mid = (lo + hi) >> 1; if (gids[mid] < g) lo = mid + 1; else hi = mid; }
        sb_ = lo;
        lo = 0; hi = NN;
        while (lo < hi) { int mid = (lo + hi) >> 1; if (gids[mid] < g + 1) lo = mid + 1; else hi = mid; }
        se_ = lo;
    }
    __syncthreads();
    int beg = sb_, end = se_;
    float acc = 0.f;
    int n = beg;
    for (; n + 3 < end; n += 4) {        // 4 independent loads per iter
        float v0 = __bfloat162float(__ldg(g_h2 + (size_t)(n + 0) * DH + f));
        float v1 = __bfloat162float(__ldg(g_h2 + (size_t)(n + 1) * DH + f));
        float v2 = __bfloat162float(__ldg(g_h2 + (size_t)(n + 2) * DH + f));
        float v3 = __bfloat162float(__ldg(g_h2 + (size_t)(n + 3) * DH + f));
        acc += (v0 + v1) + (v2 + v3);
    }
    for (; n < end; ++n)
        acc += __bfloat162float(__ldg(g_h2 + (size_t)n * DH + f));
    shg[f] = acc / fmaxf((float)(end - beg), 1.f);
    __syncthreads();

    if (f < DH2) {
        float hac = br1[f];
#pragma unroll 4
        for (int k = 0; k < DH; ++k) hac += shg[k] * Wr1[k * DH2 + f];
        float v = hac * Wr2[f];
#pragma unroll
        for (int off = 16; off > 0; off >>= 1) v += __shfl_down_sync(0xffffffffu, v, off);
        if ((f & 31) == 0) ws[f >> 5] = v;
    }
    __syncthreads();
    if (f == 0) out[g] = ws[0] + ws[1] + ws[2] + ws[3] + br2[0];
}

// ---------------- launch ----------------------------------------------------
extern "C" void kernel_launch(void* const* d_in, const int* in_sizes, int n_in,
                              void* d_out, int out_size) {
    const float* h    = (const float*)d_in[0];
    const int*   src  = (const int*)  d_in[1];
    const int*   dst  = (const int*)  d_in[2];
    const int*   gids = (const int*)  d_in[3];
    const float* W1   = (const float*)d_in[4];
    const float* b1   = (const float*)d_in[5];
    const float* W2   = (const float*)d_in[6];
    const float* b2   = (const float*)d_in[7];
    const float* Wr1  = (const float*)d_in[8];
    const float* br1  = (const float*)d_in[9];
    const float* Wr2  = (const float*)d_in[10];
    const float* br2  = (const float*)d_in[11];
    float* out = (float*)d_out;

    __nv_bfloat16 *hb, *a, *h1, *h2, *w1, *w2;
    cudaGetSymbolAddress((void**)&hb, g_hb);
    cudaGetSymbolAddress((void**)&a,  g_a);
    cudaGetSymbolAddress((void**)&h1, g_h1);
    cudaGetSymbolAddress((void**)&h2, g_h2);
    cudaGetSymbolAddress((void**)&w1, g_w1);
    cudaGetSymbolAddress((void**)&w2, g_w2);

    cudaFuncSetAttribute(k_gemm_hmma<DIN>, cudaFuncAttributeMaxDynamicSharedMemorySize, GEMM_SMEM);
    cudaFuncSetAttribute(k_gemm_hmma<DH>,  cudaFuncAttributeMaxDynamicSharedMemorySize, GEMM_SMEM);

    const dim3 ggrid((NN + 127) / 128, 2);
    const int AGG_BLK = (NN * 2 * 32 + 255) / 256;   // 2 warps per node

    // CSR build + prep (h-conv hidden inside scan/scatter kernels)
    k_zero_w<<<(ZW_TOTAL + 255) / 256, 256>>>(W1, W2);
    k_hist<<<(NE + 255) / 256, 256>>>(dst);
    k_scan_conv<<<SCAN_CONV_BLKS, 1024>>>(h);
    k_scatter_conv<<<SCAT_CONV_BLKS, 1024>>>(src, dst, h);

    // layer 1
    k_agg<DIN><<<AGG_BLK, 256>>>(hb, a);
    k_gemm_hmma<DIN><<<ggrid, 256, GEMM_SMEM>>>(a, w1, b1, h1);

    // layer 2
    k_agg<DH><<<AGG_BLK, 256>>>(h1, a);
    k_gemm_hmma<DH><<<ggrid, 256, GEMM_SMEM>>>(a, w2, b2, h2);

    // fused readout + MLP
    k_readout_mlp<<<NG, 256>>>(gids, Wr1, br1, Wr2, br2, out);
}

// round 15
// speedup vs baseline: 1.0790x; 1.0790x over previous
#include <cuda_runtime.h>
#include <cuda_bf16.h>
#include <cstdint>

#define NN   50000
#define NE   800000
#define DIN  128
#define DH   256
#define NG   256
#define DH2  128

// ---------------- scratch (device globals; no allocations allowed) ----------
__device__ __nv_bfloat16 g_hb [(size_t)NN * DIN];  // input h, bf16
__device__ __nv_bfloat16 g_a  [(size_t)NN * DH];   // aggregated features, bf16
__device__ __nv_bfloat16 g_h1 [(size_t)NN * DH];   // layer-1 output, bf16
__device__ __nv_bfloat16 g_h2 [(size_t)NN * DH];   // layer-2 output, bf16
__device__ __nv_bfloat16 g_w1 [DH * DIN];          // W1^T bf16
__device__ __nv_bfloat16 g_w2 [DH * DH];           // W2^T bf16
__device__ int g_deg[NN];
__device__ int g_rowptr[NN + 1];
__device__ int g_pos[NN];
__device__ int g_esrc[NE];

// ---------------- helpers ---------------------------------------------------
__device__ __forceinline__ uint32_t smem_u32(const void* p) {
    uint32_t a;
    asm("{ .reg .u64 t; cvta.to.shared.u64 t, %1; cvt.u32.u64 %0, t; }"
        : "=r"(a) : "l"(p));
    return a;
}

__device__ __forceinline__ void ldm_x4(uint32_t* f, uint32_t sa) {
    asm volatile("ldmatrix.sync.aligned.m8n8.x4.shared.b16 {%0,%1,%2,%3}, [%4];"
                 : "=r"(f[0]), "=r"(f[1]), "=r"(f[2]), "=r"(f[3]) : "r"(sa));
}

__device__ __forceinline__ void mma16816(float* c, const uint32_t* a, const uint32_t* b) {
    asm volatile(
        "mma.sync.aligned.m16n8k16.row.col.f32.bf16.bf16.f32 "
        "{%0,%1,%2,%3}, {%4,%5,%6,%7}, {%8,%9}, {%0,%1,%2,%3};"
        : "+f"(c[0]), "+f"(c[1]), "+f"(c[2]), "+f"(c[3])
        : "r"(a[0]), "r"(a[1]), "r"(a[2]), "r"(a[3]), "r"(b[0]), "r"(b[1]));
}

__device__ __forceinline__ void cp16(uint32_t d, const void* s, bool p) {
    asm volatile("cp.async.cg.shared.global [%0], [%1], 16, %2;"
                 :: "r"(d), "l"(s), "r"(p ? 16 : 0));
}
__device__ __forceinline__ void cp_commit() { asm volatile("cp.async.commit_group;"); }
template <int N>
__device__ __forceinline__ void cp_wait() { asm volatile("cp.async.wait_group %0;" :: "n"(N)); }

__device__ __forceinline__ void acc_u2(float* acc, uint2 u) {
    float2 a = __bfloat1622float2(*(__nv_bfloat162*)&u.x);
    float2 b = __bfloat1622float2(*(__nv_bfloat162*)&u.y);
    acc[0] += a.x; acc[1] += a.y; acc[2] += b.x; acc[3] += b.y;
}
__device__ __forceinline__ void acc_u4(float* acc, uint4 u) {
    float2 a = __bfloat1622float2(*(__nv_bfloat162*)&u.x);
    float2 b = __bfloat1622float2(*(__nv_bfloat162*)&u.y);
    float2 c = __bfloat1622float2(*(__nv_bfloat162*)&u.z);
    float2 d = __bfloat1622float2(*(__nv_bfloat162*)&u.w);
    acc[0] += a.x; acc[1] += a.y; acc[2] += b.x; acc[3] += b.y;
    acc[4] += c.x; acc[5] += c.y; acc[6] += d.x; acc[7] += d.y;
}

__device__ __forceinline__ void conv_h_item(const float* __restrict__ h, int i) {
    float4 v = __ldg((const float4*)h + i);
    __nv_bfloat16 b[4] = { __float2bfloat16(v.x), __float2bfloat16(v.y),
                           __float2bfloat16(v.z), __float2bfloat16(v.w) };
    *(uint2*)(g_hb + 4 * (size_t)i) = *(uint2*)b;
}

// ---- work split constants ---------------------------------------------------
#define PREP_H_ITEMS   (NN * DIN / 4)            // 1,600,000 float4 items
#define H1_ITEMS       614400                    // done inside k_scan_conv
#define H2_ITEMS       (PREP_H_ITEMS - H1_ITEMS) // done inside k_scatter_conv
#define PREP_W1_ITEMS  (DH * DIN)                // 32,768
#define PREP_W2_ITEMS  (DH * DH)                 // 65,536
#define HISTW_TOTAL    (NE + PREP_W1_ITEMS + PREP_W2_ITEMS)

// ---------------- zero degree ------------------------------------------------
__global__ void k_zero() {
    int i = blockIdx.x * blockDim.x + threadIdx.x;
    if (i < NN) g_deg[i] = 0;
}

// -------- edge histogram + W transposes (W rides in hist's idle capacity) ---
__global__ void k_hist_w(const int* __restrict__ dst,
                         const float* __restrict__ W1,
                         const float* __restrict__ W2) {
    int i = blockIdx.x * blockDim.x + threadIdx.x;
    if (i < NE) { atomicAdd(&g_deg[dst[i]], 1); return; }
    i -= NE;
    if (i < PREP_W1_ITEMS) {
        int n = i / DIN, k = i % DIN;
        g_w1[i] = __float2bfloat16(W1[(size_t)k * DH + n]);
        return;
    }
    i -= PREP_W1_ITEMS;
    if (i < PREP_W2_ITEMS) {
        int n = i / DH, k = i % DH;
        g_w2[i] = __float2bfloat16(W2[(size_t)k * DH + n]);
    }
}

// -------- scan (block 0) + h->bf16 conversion part 1 (blocks 1..) -----------
#define SCAN_CONV_BLKS (1 + (H1_ITEMS + 1023) / 1024)   // 601

__global__ void k_scan_conv(const float* __restrict__ h) {
    if (blockIdx.x > 0) {
        int idx = (blockIdx.x - 1) * 1024 + threadIdx.x;
        if (idx < H1_ITEMS) conv_h_item(h, idx);
        return;
    }
    // chunked single-block scan: 1024 threads * 49 elems
    const int CH = 49;
    int t = threadIdx.x;
    int beg = t * CH;
    int end = beg + CH; if (end > NN) end = NN;
    int s = 0;
    for (int i = beg; i < end; ++i) s += g_deg[i];
    int lane = t & 31, w = t >> 5;
    int v = s;
#pragma unroll
    for (int o = 1; o < 32; o <<= 1) {
        int u = __shfl_up_sync(0xffffffffu, v, o);
        if (lane >= o) v += u;
    }
    __shared__ int wsum[32];
    if (lane == 31) wsum[w] = v;
    __syncthreads();
    if (w == 0) {
        int x = wsum[lane];
#pragma unroll
        for (int o = 1; o < 32; o <<= 1) {
            int u = __shfl_up_sync(0xffffffffu, x, o);
            if (lane >= o) x += u;
        }
        wsum[lane] = x;
    }
    __syncthreads();
    int excl = v - s + (w > 0 ? wsum[w - 1] : 0);
    for (int i = beg; i < end; ++i) {
        int d = g_deg[i];
        g_rowptr[i] = excl;
        g_pos[i]    = excl;
        excl += d;
    }
    if (t == 1023) g_rowptr[NN] = wsum[31];
}

// -------- scatter + h->bf16 conversion part 2 --------------------------------
#define SCAT_BLKS      ((NE + 1023) / 1024)             // 782
#define SCAT_CONV_BLKS (SCAT_BLKS + (H2_ITEMS + 1023) / 1024)

__global__ void k_scatter_conv(const int* __restrict__ src, const int* __restrict__ dst,
                               const float* __restrict__ h) {
    if (blockIdx.x < SCAT_BLKS) {
        int e = blockIdx.x * 1024 + threadIdx.x;
        if (e < NE) {
            int p = atomicAdd(&g_pos[dst[e]], 1);
            g_esrc[p] = src[e];
        }
        return;
    }
    int idx = (blockIdx.x - SCAT_BLKS) * 1024 + threadIdx.x + H1_ITEMS;
    if (idx < PREP_H_ITEMS) conv_h_item(h, idx);
}

// ------------- warp-per-node mean aggregation, 4-edge unroll ----------------
template <int F>
__global__ __launch_bounds__(256) void k_agg(const __nv_bfloat16* __restrict__ hin,
                                             __nv_bfloat16* __restrict__ outp) {
    int warp = (blockIdx.x * blockDim.x + threadIdx.x) >> 5;
    if (warp >= NN) return;
    int lane = threadIdx.x & 31;
    int beg = g_rowptr[warp];
    int end = g_rowptr[warp + 1];
    constexpr int V = F / 32;          // bf16 per lane: 4 or 8
    float acc[V];
#pragma unroll
    for (int j = 0; j < V; ++j) acc[j] = 0.f;

    const size_t lo = (size_t)lane * V;
    int e = beg;
    for (; e + 3 < end; e += 4) {
        int s0 = g_esrc[e], s1 = g_esrc[e + 1], s2 = g_esrc[e + 2], s3 = g_esrc[e + 3];
        if constexpr (V == 4) {
            uint2 u0 = __ldg((const uint2*)(hin + (size_t)s0 * F + lo));
            uint2 u1 = __ldg((const uint2*)(hin + (size_t)s1 * F + lo));
            uint2 u2 = __ldg((const uint2*)(hin + (size_t)s2 * F + lo));
            uint2 u3 = __ldg((const uint2*)(hin + (size_t)s3 * F + lo));
            acc_u2(acc, u0); acc_u2(acc, u1); acc_u2(acc, u2); acc_u2(acc, u3);
        } else {
            uint4 u0 = __ldg((const uint4*)(hin + (size_t)s0 * F + lo));
            uint4 u1 = __ldg((const uint4*)(hin + (size_t)s1 * F + lo));
            uint4 u2 = __ldg((const uint4*)(hin + (size_t)s2 * F + lo));
            uint4 u3 = __ldg((const uint4*)(hin + (size_t)s3 * F + lo));
            acc_u4(acc, u0); acc_u4(acc, u1); acc_u4(acc, u2); acc_u4(acc, u3);
        }
    }
    for (; e < end; ++e) {
        int s0 = g_esrc[e];
        if constexpr (V == 4) {
            uint2 u0 = __ldg((const uint2*)(hin + (size_t)s0 * F + lo));
            acc_u2(acc, u0);
        } else {
            uint4 u0 = __ldg((const uint4*)(hin + (size_t)s0 * F + lo));
            acc_u4(acc, u0);
        }
    }
    float inv = (end > beg) ? (1.f / (float)(end - beg)) : 0.f;
    __nv_bfloat16 o[V];
#pragma unroll
    for (int j = 0; j < V; ++j) o[j] = __float2bfloat16(acc[j] * inv);
    if constexpr (V == 4)
        *(uint2*)(outp + (size_t)warp * F + lo) = *(uint2*)o;
    else
        *(uint4*)(outp + (size_t)warp * F + lo) = *(uint4*)o;
}

// ------- HMMA GEMM (cp.async 2-stage, BK=64): C = relu(A@B^T + b) -----------
// A: [NN x K] bf16; B: [256 x K] bf16; C: [NN x 256] bf16
#define LDA      72                 // 64 + 8 pad (bf16); row stride 144 B
#define TILE_B   (128 * LDA * 2)    // 18432 bytes
#define STAGE_B  (2 * TILE_B)       // 36864 bytes: A, B
#define GEMM_SMEM (2 * STAGE_B)     // 73728 bytes

template <int K>
__global__ __launch_bounds__(256, 2) void k_gemm_hmma(
    const __nv_bfloat16* __restrict__ A, const __nv_bfloat16* __restrict__ B,
    const float* __restrict__ bias, __nv_bfloat16* __restrict__ C)
{
    extern __shared__ char dsm[];
    const uint32_t sb0 = smem_u32(dsm);

    const int tid  = threadIdx.x;
    const int lane = tid & 31;
    const int wid  = tid >> 5;
    const int wm   = (wid >> 1) * 32;
    const int wn   = (wid & 1) * 64;
    const int m0   = blockIdx.x * 128;
    const int n0   = blockIdx.y * 128;

    float c[2][8][4];
#pragma unroll
    for (int i = 0; i < 2; ++i)
#pragma unroll
        for (int j = 0; j < 8; ++j)
#pragma unroll
            for (int q = 0; q < 4; ++q) c[i][j][q] = 0.f;

    const int aq = lane >> 3, ar = lane & 7;
    const int a_row = ar + (aq & 1) * 8;
    const int a_col = (aq >> 1) * 8;
    uint32_t aoff[2];
#pragma unroll
    for (int i = 0; i < 2; ++i)
        aoff[i] = (uint32_t)(((wm + i * 16 + a_row) * LDA + a_col) * 2);
    const int b_row = (aq >> 1) * 8 + ar;
    const int b_col = (aq & 1) * 8;
    uint32_t boff[4];
#pragma unroll
    for (int jp = 0; jp < 4; ++jp)
        boff[jp] = (uint32_t)(((wn + jp * 16 + b_row) * LDA + b_col) * 2);

    auto load_stage = [&](int k0, int s) {
        uint32_t base = sb0 + (uint32_t)s * STAGE_B;
#pragma unroll
        for (int t = 0; t < 4; ++t) {
            int idx = t * 256 + tid;          // 0..1023: 128 rows x 64 cols
            int r = idx >> 3, cB = (idx & 7) * 8;
            uint32_t so = (uint32_t)((r * LDA + cB) * 2);
            int gr = m0 + r;
            bool ap = gr < NN;
            int grc = ap ? gr : (NN - 1);
            cp16(base + so, A + (size_t)grc * K + k0 + cB, ap);
            cp16(base + TILE_B + so, B + (size_t)(n0 + r) * K + k0 + cB, true);
        }
        cp_commit();
    };

    const int NCH = K / 64;                  // 2 or 4
    load_stage(0, 0);
    load_stage(64, 1);
    for (int ch = 0; ch < NCH; ++ch) {
        if (ch + 1 < NCH) cp_wait<1>(); else cp_wait<0>();
        __syncthreads();
        uint32_t base = sb0 + (uint32_t)(ch & 1) * STAGE_B;
        uint32_t sa = base, sbm = base + TILE_B;
#pragma unroll
        for (int ks = 0; ks < 4; ++ks) {
            uint32_t af[2][4];
#pragma unroll
            for (int i = 0; i < 2; ++i) ldm_x4(af[i], sa + aoff[i] + ks * 32);
#pragma unroll
            for (int jp = 0; jp < 4; ++jp) {
                uint32_t bf[4];
                ldm_x4(bf, sbm + boff[jp] + ks * 32);
#pragma unroll
                for (int i = 0; i < 2; ++i) {
#pragma unroll
                    for (int jj = 0; jj < 2; ++jj)
                        mma16816(c[i][jp * 2 + jj], af[i], bf + jj * 2);
                }
            }
        }
        __syncthreads();
        if (ch + 2 < NCH) load_stage((ch + 2) * 64, ch & 1);
    }

    // epilogue: bias + relu, bf16 store
    const int g   = lane >> 2;
    const int tig = lane & 3;
#pragma unroll
    for (int i = 0; i < 2; ++i) {
#pragma unroll
        for (int j = 0; j < 8; ++j) {
            int col  = n0 + wn + j * 8 + 2 * tig;
            float b0 = bias[col], b1 = bias[col + 1];
            int r0 = m0 + wm + i * 16 + g;
            if (r0 < NN) {
                __nv_bfloat162 o = __floats2bfloat162_rn(
                    fmaxf(c[i][j][0] + b0, 0.f), fmaxf(c[i][j][1] + b1, 0.f));
                *(__nv_bfloat162*)(C + (size_t)r0 * 256 + col) = o;
            }
            int r1 = r0 + 8;
            if (r1 < NN) {
                __nv_bfloat162 o = __floats2bfloat162_rn(
                    fmaxf(c[i][j][2] + b0, 0.f), fmaxf(c[i][j][3] + b1, 0.f));
                *(__nv_bfloat162*)(C + (size_t)r1 * 256 + col) = o;
            }
        }
    }
}

// -------- fused per-graph readout + MLP (graph_ids sorted) ------------------
__global__ __launch_bounds__(256) void k_readout_mlp(
    const int* __restrict__ gids,
    const float* __restrict__ Wr1, const float* __restrict__ br1,
    const float* __restrict__ Wr2, const float* __restrict__ br2,
    float* __restrict__ out)
{
    int g = blockIdx.x;
    int f = threadIdx.x;                 // 256 threads
    __shared__ int sb_, se_;
    __shared__ float shg[DH];
    __shared__ float ws[4];
    if (f == 0) {
        int lo = 0, hi = NN;
        while (lo < hi) { int mid = (lo + hi) >> 1; if (gids[mid] < g) lo = mid + 1; else hi = mid; }
        sb_ = lo;
        lo = 0; hi = NN;
        while (lo < hi) { int mid = (lo + hi) >> 1; if (gids[mid] < g + 1) lo = mid + 1; else hi = mid; }
        se_ = lo;
    }
    __syncthreads();
    int beg = sb_, end = se_;
    float acc = 0.f;
    int n = beg;
    for (; n + 3 < end; n += 4) {        // 4 independent loads per iter
        float v0 = __bfloat162float(__ldg(g_h2 + (size_t)(n + 0) * DH + f));
        float v1 = __bfloat162float(__ldg(g_h2 + (size_t)(n + 1) * DH + f));
        float v2 = __bfloat162float(__ldg(g_h2 + (size_t)(n + 2) * DH + f));
        float v3 = __bfloat162float(__ldg(g_h2 + (size_t)(n + 3) * DH + f));
        acc += (v0 + v1) + (v2 + v3);
    }
    for (; n < end; ++n)
        acc += __bfloat162float(__ldg(g_h2 + (size_t)n * DH + f));
    shg[f] = acc / fmaxf((float)(end - beg), 1.f);
    __syncthreads();

    if (f < DH2) {
        float hac = br1[f];
#pragma unroll 4
        for (int k = 0; k < DH; ++k) hac += shg[k] * Wr1[k * DH2 + f];
        float v = hac * Wr2[f];
#pragma unroll
        for (int off = 16; off > 0; off >>= 1) v += __shfl_down_sync(0xffffffffu, v, off);
        if ((f & 31) == 0) ws[f >> 5] = v;
    }
    __syncthreads();
    if (f == 0) out[g] = ws[0] + ws[1] + ws[2] + ws[3] + br2[0];
}

// ---------------- launch ----------------------------------------------------
extern "C" void kernel_launch(void* const* d_in, const int* in_sizes, int n_in,
                              void* d_out, int out_size) {
    const float* h    = (const float*)d_in[0];
    const int*   src  = (const int*)  d_in[1];
    const int*   dst  = (const int*)  d_in[2];
    const int*   gids = (const int*)  d_in[3];
    const float* W1   = (const float*)d_in[4];
    const float* b1   = (const float*)d_in[5];
    const float* W2   = (const float*)d_in[6];
    const float* b2   = (const float*)d_in[7];
    const float* Wr1  = (const float*)d_in[8];
    const float* br1  = (const float*)d_in[9];
    const float* Wr2  = (const float*)d_in[10];
    const float* br2  = (const float*)d_in[11];
    float* out = (float*)d_out;

    __nv_bfloat16 *hb, *a, *h1, *h2, *w1, *w2;
    cudaGetSymbolAddress((void**)&hb, g_hb);
    cudaGetSymbolAddress((void**)&a,  g_a);
    cudaGetSymbolAddress((void**)&h1, g_h1);
    cudaGetSymbolAddress((void**)&h2, g_h2);
    cudaGetSymbolAddress((void**)&w1, g_w1);
    cudaGetSymbolAddress((void**)&w2, g_w2);

    cudaFuncSetAttribute(k_gemm_hmma<DIN>, cudaFuncAttributeMaxDynamicSharedMemorySize, GEMM_SMEM);
    cudaFuncSetAttribute(k_gemm_hmma<DH>,  cudaFuncAttributeMaxDynamicSharedMemorySize, GEMM_SMEM);

    const dim3 ggrid((NN + 127) / 128, 2);
    const int AGG_BLK = (NN * 32 + 255) / 256;   // warp per node

    // CSR build + prep (W-prep hidden in hist, h-conv hidden in scan/scatter)
    k_zero<<<(NN + 255) / 256, 256>>>();
    k_hist_w<<<(HISTW_TOTAL + 255) / 256, 256>>>(dst, W1, W2);
    k_scan_conv<<<SCAN_CONV_BLKS, 1024>>>(h);
    k_scatter_conv<<<SCAT_CONV_BLKS, 1024>>>(src, dst, h);

    // layer 1
    k_agg<DIN><<<AGG_BLK, 256>>>(hb, a);
    k_gemm_hmma<DIN><<<ggrid, 256, GEMM_SMEM>>>(a, w1, b1, h1);

    // layer 2
    k_agg<DH><<<AGG_BLK, 256>>>(h1, a);
    k_gemm_hmma<DH><<<ggrid, 256, GEMM_SMEM>>>(a, w2, b2, h2);

    // fused readout + MLP
    k_readout_mlp<<<NG, 256>>>(gids, Wr1, br1, Wr2, br2, out);
}